// round 15
// baseline (speedup 1.0000x reference)
#include <cuda_runtime.h>
#include <cuda_bf16.h>
#include <cuda_fp16.h>
#include <cstdint>

#define IN_DIM 256
#define HD 128          // NHEADS * ODIM
#define NHEADS 4
#define ODIM 32
#define NEG_SLOPE 0.2f
#define N_NODES_MAX 100000
#define N_EDGES_MAX 1600000

// ---------------- scratch (device globals; no allocation allowed) ------------
__device__ __align__(16) __half g_fth[(size_t)N_NODES_MAX * HD];   // ft as fp16 (agg-only consumer)
__device__ __align__(16) float g_el  [N_NODES_MAX * NHEADS];
__device__ __align__(16) float g_er  [N_NODES_MAX * NHEADS];
__device__ __align__(16) float g_esum[N_NODES_MAX * NHEADS];
__device__ __align__(16) float g_inv [N_NODES_MAX * NHEADS];
__device__ __align__(16) float g_eexp[(size_t)N_EDGES_MAX * NHEADS];
// W pre-split into bf16 hi/lo, row-major [k=256][n=128]
__device__ int4 g_Bh4[IN_DIM * HD / 8];
__device__ int4 g_Bl4[IN_DIM * HD / 8];

// ---------------- helpers -----------------------------------------------------
__device__ __forceinline__ uint32_t smem_to_u32(const void* p) {
    uint32_t a;
    asm("{ .reg .u64 t; cvta.to.shared.u64 t, %1; cvt.u32.u64 %0, t; }" : "=r"(a) : "l"(p));
    return a;
}
__device__ __forceinline__ void bsplit(float v, __nv_bfloat16& hi, __nv_bfloat16& lo) {
    hi = __float2bfloat16(v);
    lo = __float2bfloat16(v - __bfloat162float(hi));
}
__device__ __forceinline__ uint32_t pack2(__nv_bfloat16 a, __nv_bfloat16 b) {
    uint16_t ua = *(uint16_t*)&a, ub = *(uint16_t*)&b;
    return (uint32_t)ua | ((uint32_t)ub << 16);
}
__device__ __forceinline__ void ldsm_x4(uint32_t* r, uint32_t addr) {
    asm volatile("ldmatrix.sync.aligned.m8n8.x4.shared.b16 {%0,%1,%2,%3}, [%4];"
                 : "=r"(r[0]), "=r"(r[1]), "=r"(r[2]), "=r"(r[3]) : "r"(addr));
}
__device__ __forceinline__ void ldsm_x2t(uint32_t* r, uint32_t addr) {
    asm volatile("ldmatrix.sync.aligned.m8n8.x2.trans.shared.b16 {%0,%1}, [%2];"
                 : "=r"(r[0]), "=r"(r[1]) : "r"(addr));
}
__device__ __forceinline__ void mma16816(float* c, const uint32_t* a, const uint32_t* b) {
    asm volatile("mma.sync.aligned.m16n8k16.row.col.f32.bf16.bf16.f32 "
                 "{%0,%1,%2,%3}, {%4,%5,%6,%7}, {%8,%9}, {%0,%1,%2,%3};"
                 : "+f"(c[0]), "+f"(c[1]), "+f"(c[2]), "+f"(c[3])
                 : "r"(a[0]), "r"(a[1]), "r"(a[2]), "r"(a[3]), "r"(b[0]), "r"(b[1]));
}
__device__ __forceinline__ void cp_async16(uint32_t daddr, const void* gaddr) {
    asm volatile("cp.async.cg.shared.global [%0], [%1], 16;" :: "r"(daddr), "l"(gaddr));
}
__device__ __forceinline__ void cp_commit() {
    asm volatile("cp.async.commit_group;" ::: "memory");
}
__device__ __forceinline__ void cp_wait0() {
    asm volatile("cp.async.wait_group 0;" ::: "memory");
}

// ---------------- K0a/K0b/K0c: init split (positions GEMM as ncu launch #4) ---
__global__ void zero_esum_kernel(int n4) {
    int i = blockIdx.x * blockDim.x + threadIdx.x;
    int stride = gridDim.x * blockDim.x;
    for (int j = i; j < n4; j += stride) g_esum[j] = 0.0f;
}
__global__ void zero_out_kernel(float* __restrict__ out, int no) {
    int i = blockIdx.x * blockDim.x + threadIdx.x;
    int stride = gridDim.x * blockDim.x;
    for (int j = i; j < no; j += stride) out[j] = 0.0f;
}
__global__ void wprep_kernel(const float* __restrict__ W) {
    int i = blockIdx.x * blockDim.x + threadIdx.x;
    if (i >= IN_DIM * HD) return;
    __nv_bfloat16 hi, lo;
    bsplit(W[i], hi, lo);
    ((__nv_bfloat16*)g_Bh4)[i] = hi;
    ((__nv_bfloat16*)g_Bl4)[i] = lo;
}

// ---------------- K1: pipelined mma.sync bf16-split GEMM + fused el/er -------
// BM=64 (2 blocks/SM), block 64x128, warp tile 32x32, K chunks of 32.
#define SAP 40     // smem A row stride (halves)
#define SBP 136    // smem B row stride (halves)
#define A_SPLIT_BYTES (64 * SAP * 2)         // 5120
#define A_STAGE_BYTES (2 * A_SPLIT_BYTES)    // 10240 (hi + lo)
#define B_SPLIT_BYTES (32 * SBP * 2)         // 8704
#define B_STAGE_BYTES (2 * B_SPLIT_BYTES)    // 17408
#define OFF_B   (2 * A_STAGE_BYTES)          // 20480
#define OFF_AL  (OFF_B + 2 * B_STAGE_BYTES)  // 55296
#define OFF_AR  (OFF_AL + 512)
#define GEMM_SMEM_TOTAL (OFF_AR + 512)       // 56320

__global__ void __launch_bounds__(256) gemm_mma_kernel(
    const float* __restrict__ A, const float* __restrict__ al,
    const float* __restrict__ ar, int M)
{
    extern __shared__ char smem[];
    uint32_t smem_u = smem_to_u32(smem);
    int tid = threadIdx.x, wid = tid >> 5, lane = tid & 31;
    int warp_m = wid & 1, warp_n = wid >> 1;    // 2 x 4 warp grid; warp_n == head
    int block_row = blockIdx.x * 64;

    float* sal = (float*)(smem + OFF_AL);
    float* sar = (float*)(smem + OFF_AR);
    if (tid < HD) sal[tid] = al[tid];
    else          sar[tid - HD] = ar[tid - HD];

    int arow[2], aseg[2];
#pragma unroll
    for (int i = 0; i < 2; i++) {
        int idx = tid + i * 256;
        arow[i] = idx >> 3;
        aseg[i] = idx & 7;
    }
    int brow[2], bseg[2];
#pragma unroll
    for (int i = 0; i < 2; i++) {
        int idx = tid + i * 256;
        brow[i] = idx >> 4;
        bseg[i] = idx & 15;
    }

    float4 av[2];
    auto load_A = [&](int chunk) {
#pragma unroll
        for (int i = 0; i < 2; i++) {
            int gr = block_row + arow[i];
            av[i] = make_float4(0.f, 0.f, 0.f, 0.f);
            if (gr < M)
                av[i] = *(const float4*)&A[(size_t)gr * IN_DIM + chunk * 32 + aseg[i] * 4];
        }
    };
    auto store_A = [&](int stage) {
#pragma unroll
        for (int i = 0; i < 2; i++) {
            __nv_bfloat16 hx, lx, hy, ly, hz, lz, hw, lw;
            bsplit(av[i].x, hx, lx); bsplit(av[i].y, hy, ly);
            bsplit(av[i].z, hz, lz); bsplit(av[i].w, hw, lw);
            uint32_t off = (uint32_t)(arow[i] * (SAP * 2) + aseg[i] * 8);
            *(uint2*)(smem + stage * A_STAGE_BYTES + off) = make_uint2(pack2(hx, hy), pack2(hz, hw));
            *(uint2*)(smem + stage * A_STAGE_BYTES + A_SPLIT_BYTES + off) = make_uint2(pack2(lx, ly), pack2(lz, lw));
        }
    };
    auto load_B_async = [&](int chunk, int stage) {
        uint32_t bh = smem_u + OFF_B + stage * B_STAGE_BYTES;
        uint32_t bl = bh + B_SPLIT_BYTES;
#pragma unroll
        for (int i = 0; i < 2; i++) {
            uint32_t off = (uint32_t)(brow[i] * (SBP * 2) + bseg[i] * 16);
            int gsrc = (chunk * 32 + brow[i]) * (HD / 8) + bseg[i];
            cp_async16(bh + off, &g_Bh4[gsrc]);
            cp_async16(bl + off, &g_Bl4[gsrc]);
        }
        cp_commit();
    };

    float acc[2][4][4];
#pragma unroll
    for (int im = 0; im < 2; im++)
#pragma unroll
        for (int in = 0; in < 4; in++)
#pragma unroll
            for (int j = 0; j < 4; j++) acc[im][in][j] = 0.0f;

    // prologue: fill stage 0
    load_A(0);
    load_B_async(0, 0);
    store_A(0);
    cp_wait0();
    __syncthreads();

    int cur = 0;
    for (int chunk = 0; chunk < 8; chunk++) {
        int nxt = cur ^ 1;
        if (chunk < 7) {
            load_A(chunk + 1);
            load_B_async(chunk + 1, nxt);
        }
        uint32_t ah_b = smem_u + cur * A_STAGE_BYTES;
        uint32_t al_b = ah_b + A_SPLIT_BYTES;
        uint32_t bh_b = smem_u + OFF_B + cur * B_STAGE_BYTES;
        uint32_t bl_b = bh_b + B_SPLIT_BYTES;
#pragma unroll
        for (int ks = 0; ks < 2; ks++) {
            uint32_t bh[4][2], bl[4][2];
#pragma unroll
            for (int in = 0; in < 4; in++) {
                uint32_t off = (uint32_t)((ks * 16 + (lane & 15)) * SBP + warp_n * 32 + in * 8) * 2;
                ldsm_x2t(bh[in], bh_b + off);
                ldsm_x2t(bl[in], bl_b + off);
            }
            uint32_t ahf[2][4], alf[2][4];
#pragma unroll
            for (int im = 0; im < 2; im++) {
                uint32_t row = warp_m * 32 + im * 16 + (lane & 15);
                uint32_t off = (row * SAP + ks * 16 + (lane >> 4) * 8) * 2;
                ldsm_x4(ahf[im], ah_b + off);
                ldsm_x4(alf[im], al_b + off);
            }
#pragma unroll
            for (int im = 0; im < 2; im++)
#pragma unroll
                for (int in = 0; in < 4; in++) {
                    mma16816(acc[im][in], ahf[im], bh[in]);
                    mma16816(acc[im][in], ahf[im], bl[in]);
                    mma16816(acc[im][in], alf[im], bh[in]);
                }
        }
        if (chunk < 7) {
            store_A(nxt);
            cp_wait0();
        }
        __syncthreads();
        cur = nxt;
    }

    // ---- epilogue: store ft fp16 + fused el/er (warp_n == head)
#pragma unroll
    for (int im = 0; im < 2; im++) {
        int r0 = block_row + warp_m * 32 + im * 16 + (lane >> 2);
        int r1 = r0 + 8;
        float sl0 = 0.f, sr0 = 0.f, sl1 = 0.f, sr1 = 0.f;
#pragma unroll
        for (int in = 0; in < 4; in++) {
            int col = warp_n * 32 + in * 8 + (lane & 3) * 2;
            float c0 = acc[im][in][0], c1 = acc[im][in][1];
            float c2 = acc[im][in][2], c3 = acc[im][in][3];
            float a0 = sal[col], a1 = sal[col + 1];
            float b0 = sar[col], b1 = sar[col + 1];
            sl0 += c0 * a0 + c1 * a1;  sr0 += c0 * b0 + c1 * b1;
            sl1 += c2 * a0 + c3 * a1;  sr1 += c2 * b0 + c3 * b1;
            if (r0 < M) *(__half2*)&g_fth[(size_t)r0 * HD + col] = __floats2half2_rn(c0, c1);
            if (r1 < M) *(__half2*)&g_fth[(size_t)r1 * HD + col] = __floats2half2_rn(c2, c3);
        }
#pragma unroll
        for (int o = 1; o <= 2; o <<= 1) {
            sl0 += __shfl_xor_sync(0xffffffffu, sl0, o);
            sr0 += __shfl_xor_sync(0xffffffffu, sr0, o);
            sl1 += __shfl_xor_sync(0xffffffffu, sl1, o);
            sr1 += __shfl_xor_sync(0xffffffffu, sr1, o);
        }
        if ((lane & 3) == 0) {
            if (r0 < M) { g_el[r0 * NHEADS + warp_n] = sl0; g_er[r0 * NHEADS + warp_n] = sr0; }
            if (r1 < M) { g_el[r1 * NHEADS + warp_n] = sl1; g_er[r1 * NHEADS + warp_n] = sr1; }
        }
    }
}

// ---------------- K4: edge exp + segment sum (2 edges/thread, vector RED) ----
__global__ void edge_exp_kernel(const int* __restrict__ src, const int* __restrict__ dst,
                                int E) {
    int half = (E + 1) >> 1;
    int t = blockIdx.x * blockDim.x + threadIdx.x;
    if (t >= half) return;
    int e2 = t + half;
    int s0 = __ldg(&src[t]), d0 = __ldg(&dst[t]);
    int s1 = 0, d1 = 0;
    bool has2 = (e2 < E);
    if (has2) { s1 = __ldg(&src[e2]); d1 = __ldg(&dst[e2]); }
    float4 l0 = *(const float4*)&g_el[s0 * NHEADS];
    float4 r0 = *(const float4*)&g_er[d0 * NHEADS];
    float4 l1 = make_float4(0, 0, 0, 0), r1 = make_float4(0, 0, 0, 0);
    if (has2) { l1 = *(const float4*)&g_el[s1 * NHEADS]; r1 = *(const float4*)&g_er[d1 * NHEADS]; }

    float a0 = l0.x + r0.x, a1 = l0.y + r0.y, a2 = l0.z + r0.z, a3 = l0.w + r0.w;
    a0 = a0 > 0.f ? a0 : NEG_SLOPE * a0;
    a1 = a1 > 0.f ? a1 : NEG_SLOPE * a1;
    a2 = a2 > 0.f ? a2 : NEG_SLOPE * a2;
    a3 = a3 > 0.f ? a3 : NEG_SLOPE * a3;
    // logits bounded (|x| << 88): exp without max shift is mathematically identical
    float ea0 = __expf(a0), ea1 = __expf(a1), ea2 = __expf(a2), ea3 = __expf(a3);
    *(float4*)&g_eexp[(size_t)t * NHEADS] = make_float4(ea0, ea1, ea2, ea3);
    asm volatile("red.global.add.v4.f32 [%0], {%1, %2, %3, %4};"
                 :: "l"(&g_esum[d0 * NHEADS]), "f"(ea0), "f"(ea1), "f"(ea2), "f"(ea3) : "memory");

    if (has2) {
        float b0 = l1.x + r1.x, b1 = l1.y + r1.y, b2 = l1.z + r1.z, b3 = l1.w + r1.w;
        b0 = b0 > 0.f ? b0 : NEG_SLOPE * b0;
        b1 = b1 > 0.f ? b1 : NEG_SLOPE * b1;
        b2 = b2 > 0.f ? b2 : NEG_SLOPE * b2;
        b3 = b3 > 0.f ? b3 : NEG_SLOPE * b3;
        float eb0 = __expf(b0), eb1 = __expf(b1), eb2 = __expf(b2), eb3 = __expf(b3);
        *(float4*)&g_eexp[(size_t)e2 * NHEADS] = make_float4(eb0, eb1, eb2, eb3);
        asm volatile("red.global.add.v4.f32 [%0], {%1, %2, %3, %4};"
                     :: "l"(&g_esum[d1 * NHEADS]), "f"(eb0), "f"(eb1), "f"(eb2), "f"(eb3) : "memory");
    }
}

// ---------------- K5: reciprocal ---------------------------------------------
__global__ void inv_kernel(int n4) {
    int i = blockIdx.x * blockDim.x + threadIdx.x;
    if (i >= n4) return;
    float s = g_esum[i];
    g_inv[i] = (s > 0.f) ? (1.0f / s) : 0.0f;
}

// ---------------- K6: weighted aggregation (8 threads/edge, half2 math) ------
// R7/R11 shape: thread j of 8 owns output dims [4j,4j+4): per head loads one
// uint2 (4 halves); weights folded via HFMA2 (halves arithmetic instruction
// count vs FFMA+cvt); one v4 RED.
__global__ void agg_kernel(const int* __restrict__ src, const int* __restrict__ dst,
                           float* __restrict__ out, int E) {
    int gtid = blockIdx.x * blockDim.x + threadIdx.x;
    int e = gtid >> 3;
    int j = gtid & 7;
    if (e >= E) return;
    int s = __ldg(&src[e]), d = __ldg(&dst[e]);
    float4 ex = *(const float4*)&g_eexp[(size_t)e * NHEADS];
    float4 iv = *(const float4*)&g_inv[d * NHEADS];
    __half2 w0 = __float2half2_rn(0.25f * ex.x * iv.x);
    __half2 w1 = __float2half2_rn(0.25f * ex.y * iv.y);
    __half2 w2 = __float2half2_rn(0.25f * ex.z * iv.z);
    __half2 w3 = __float2half2_rn(0.25f * ex.w * iv.w);
    const uint2* f2 = (const uint2*)&g_fth[(size_t)s * HD];
    uint2 u0 = f2[j], u1 = f2[8 + j], u2 = f2[16 + j], u3 = f2[24 + j];
    __half2 ax = __hmul2(w0, *(__half2*)&u0.x);
    ax = __hfma2(w1, *(__half2*)&u1.x, ax);
    ax = __hfma2(w2, *(__half2*)&u2.x, ax);
    ax = __hfma2(w3, *(__half2*)&u3.x, ax);
    __half2 ay = __hmul2(w0, *(__half2*)&u0.y);
    ay = __hfma2(w1, *(__half2*)&u1.y, ay);
    ay = __hfma2(w2, *(__half2*)&u2.y, ay);
    ay = __hfma2(w3, *(__half2*)&u3.y, ay);
    float2 vx = __half22float2(ax);
    float2 vy = __half22float2(ay);
    float* op = &out[(size_t)d * ODIM + j * 4];
    asm volatile("red.global.add.v4.f32 [%0], {%1, %2, %3, %4};"
                 :: "l"(op), "f"(vx.x), "f"(vx.y), "f"(vy.x), "f"(vy.y) : "memory");
}

// ---------------- launch ------------------------------------------------------
extern "C" void kernel_launch(void* const* d_in, const int* in_sizes, int n_in,
                              void* d_out, int out_size) {
    const float* feat = (const float*)d_in[0];
    const float* W    = (const float*)d_in[1];
    const float* al   = (const float*)d_in[2];
    const float* ar   = (const float*)d_in[3];
    const int*   src  = (const int*)d_in[4];
    const int*   dst  = (const int*)d_in[5];
    float*       out  = (float*)d_out;

    int n = in_sizes[0] / IN_DIM;
    int E = in_sizes[4];

    // K0a/K0b/K0c: init split so GEMM is ncu launch #4
    {
        int n4 = n * NHEADS;
        zero_esum_kernel<<<(n4 + 255) / 256, 256>>>(n4);
        int no = n * ODIM;
        zero_out_kernel<<<(no + 255) / 256, 256>>>(out, no);
        wprep_kernel<<<(IN_DIM * HD + 255) / 256, 256>>>(W);
    }
    // K1: pipelined mma.sync GEMM + fused el/er (BM=64, 2 blocks/SM)
    {
        cudaFuncSetAttribute(gemm_mma_kernel,
                             cudaFuncAttributeMaxDynamicSharedMemorySize, GEMM_SMEM_TOTAL);
        gemm_mma_kernel<<<(n + 63) / 64, 256, GEMM_SMEM_TOTAL>>>(feat, al, ar, n);
    }
    // K4: exp + segment sum (2 edges/thread)
    {
        int half = (E + 1) >> 1;
        edge_exp_kernel<<<(half + 255) / 256, 256>>>(src, dst, E);
    }
    // K5: reciprocal
    {
        int n4 = n * NHEADS;
        inv_kernel<<<(n4 + 255) / 256, 256>>>(n4);
    }
    // K6: aggregation (8 threads per edge, fp16 ft, half2 weight math)
    {
        long long totalThreads = (long long)E * 8;
        int blocks = (int)((totalThreads + 255) / 256);
        agg_kernel<<<blocks, 256>>>(src, dst, out, E);
    }
}

// round 16
// speedup vs baseline: 1.0401x; 1.0401x over previous
#include <cuda_runtime.h>
#include <cuda_bf16.h>
#include <cuda_fp16.h>
#include <cstdint>

#define IN_DIM 256
#define HD 128          // NHEADS * ODIM
#define NHEADS 4
#define ODIM 32
#define NEG_SLOPE 0.2f
#define N_NODES_MAX 100000
#define N_EDGES_MAX 1600000

// ---------------- scratch (device globals; no allocation allowed) ------------
__device__ __align__(16) __half g_fth[(size_t)N_NODES_MAX * HD];   // ft as fp16 (agg-only consumer)
__device__ __align__(16) float g_el  [N_NODES_MAX * NHEADS];
__device__ __align__(16) float g_er  [N_NODES_MAX * NHEADS];
__device__ __align__(16) float g_esum[N_NODES_MAX * NHEADS];
__device__ __align__(16) float g_inv [N_NODES_MAX * NHEADS];
__device__ __align__(16) float g_eexp[(size_t)N_EDGES_MAX * NHEADS];
// W pre-split into bf16 hi/lo, row-major [k=256][n=128]
__device__ int4 g_Bh4[IN_DIM * HD / 8];
__device__ int4 g_Bl4[IN_DIM * HD / 8];

// ---------------- helpers -----------------------------------------------------
__device__ __forceinline__ uint32_t smem_to_u32(const void* p) {
    uint32_t a;
    asm("{ .reg .u64 t; cvta.to.shared.u64 t, %1; cvt.u32.u64 %0, t; }" : "=r"(a) : "l"(p));
    return a;
}
__device__ __forceinline__ void bsplit(float v, __nv_bfloat16& hi, __nv_bfloat16& lo) {
    hi = __float2bfloat16(v);
    lo = __float2bfloat16(v - __bfloat162float(hi));
}
__device__ __forceinline__ uint32_t pack2(__nv_bfloat16 a, __nv_bfloat16 b) {
    uint16_t ua = *(uint16_t*)&a, ub = *(uint16_t*)&b;
    return (uint32_t)ua | ((uint32_t)ub << 16);
}
__device__ __forceinline__ void ldsm_x4(uint32_t* r, uint32_t addr) {
    asm volatile("ldmatrix.sync.aligned.m8n8.x4.shared.b16 {%0,%1,%2,%3}, [%4];"
                 : "=r"(r[0]), "=r"(r[1]), "=r"(r[2]), "=r"(r[3]) : "r"(addr));
}
__device__ __forceinline__ void ldsm_x4t(uint32_t* r, uint32_t addr) {
    asm volatile("ldmatrix.sync.aligned.m8n8.x4.trans.shared.b16 {%0,%1,%2,%3}, [%4];"
                 : "=r"(r[0]), "=r"(r[1]), "=r"(r[2]), "=r"(r[3]) : "r"(addr));
}
__device__ __forceinline__ void mma16816(float* c, const uint32_t* a, const uint32_t* b) {
    asm volatile("mma.sync.aligned.m16n8k16.row.col.f32.bf16.bf16.f32 "
                 "{%0,%1,%2,%3}, {%4,%5,%6,%7}, {%8,%9}, {%0,%1,%2,%3};"
                 : "+f"(c[0]), "+f"(c[1]), "+f"(c[2]), "+f"(c[3])
                 : "r"(a[0]), "r"(a[1]), "r"(a[2]), "r"(a[3]), "r"(b[0]), "r"(b[1]));
}
__device__ __forceinline__ void cp_async16(uint32_t daddr, const void* gaddr) {
    asm volatile("cp.async.cg.shared.global [%0], [%1], 16;" :: "r"(daddr), "l"(gaddr));
}
__device__ __forceinline__ void cp_commit() {
    asm volatile("cp.async.commit_group;" ::: "memory");
}
__device__ __forceinline__ void cp_wait0() {
    asm volatile("cp.async.wait_group 0;" ::: "memory");
}

// ---------------- K0: init esum + output + W split (merged) ------------------
__global__ void init_prep_kernel(float* __restrict__ out, const float* __restrict__ W, int n) {
    int i = blockIdx.x * blockDim.x + threadIdx.x;
    int stride = gridDim.x * blockDim.x;
    int n4 = n * NHEADS;
    for (int j = i; j < n4; j += stride) g_esum[j] = 0.0f;
    int no = n * ODIM;
    for (int j = i; j < no; j += stride) out[j] = 0.0f;
    for (int j = i; j < IN_DIM * HD; j += stride) {
        __nv_bfloat16 hi, lo;
        bsplit(W[j], hi, lo);
        ((__nv_bfloat16*)g_Bh4)[j] = hi;
        ((__nv_bfloat16*)g_Bl4)[j] = lo;
    }
}

// ---------------- K1: pipelined mma.sync bf16-split GEMM + fused el/er -------
// BM=64, block 64x128, warp tile 32x32, K chunks of 32; B frags via ldsm.x4.trans.
#define SAP 40     // smem A row stride (halves)
#define SBP 136    // smem B row stride (halves)
#define A_SPLIT_BYTES (64 * SAP * 2)         // 5120
#define A_STAGE_BYTES (2 * A_SPLIT_BYTES)    // 10240 (hi + lo)
#define B_SPLIT_BYTES (32 * SBP * 2)         // 8704
#define B_STAGE_BYTES (2 * B_SPLIT_BYTES)    // 17408
#define OFF_B   (2 * A_STAGE_BYTES)          // 20480
#define OFF_AL  (OFF_B + 2 * B_STAGE_BYTES)  // 55296
#define OFF_AR  (OFF_AL + 512)
#define GEMM_SMEM_TOTAL (OFF_AR + 512)       // 56320

__global__ void __launch_bounds__(256) gemm_mma_kernel(
    const float* __restrict__ A, const float* __restrict__ al,
    const float* __restrict__ ar, int M)
{
    extern __shared__ char smem[];
    uint32_t smem_u = smem_to_u32(smem);
    int tid = threadIdx.x, wid = tid >> 5, lane = tid & 31;
    int warp_m = wid & 1, warp_n = wid >> 1;    // 2 x 4 warp grid; warp_n == head
    int block_row = blockIdx.x * 64;

    float* sal = (float*)(smem + OFF_AL);
    float* sar = (float*)(smem + OFF_AR);
    if (tid < HD) sal[tid] = al[tid];
    else          sar[tid - HD] = ar[tid - HD];

    int arow[2], aseg[2];
#pragma unroll
    for (int i = 0; i < 2; i++) {
        int idx = tid + i * 256;
        arow[i] = idx >> 3;
        aseg[i] = idx & 7;
    }
    int brow[2], bseg[2];
#pragma unroll
    for (int i = 0; i < 2; i++) {
        int idx = tid + i * 256;
        brow[i] = idx >> 4;
        bseg[i] = idx & 15;
    }

    float4 av[2];
    auto load_A = [&](int chunk) {
#pragma unroll
        for (int i = 0; i < 2; i++) {
            int gr = block_row + arow[i];
            av[i] = make_float4(0.f, 0.f, 0.f, 0.f);
            if (gr < M)
                av[i] = *(const float4*)&A[(size_t)gr * IN_DIM + chunk * 32 + aseg[i] * 4];
        }
    };
    auto store_A = [&](int stage) {
#pragma unroll
        for (int i = 0; i < 2; i++) {
            __nv_bfloat16 hx, lx, hy, ly, hz, lz, hw, lw;
            bsplit(av[i].x, hx, lx); bsplit(av[i].y, hy, ly);
            bsplit(av[i].z, hz, lz); bsplit(av[i].w, hw, lw);
            uint32_t off = (uint32_t)(arow[i] * (SAP * 2) + aseg[i] * 8);
            *(uint2*)(smem + stage * A_STAGE_BYTES + off) = make_uint2(pack2(hx, hy), pack2(hz, hw));
            *(uint2*)(smem + stage * A_STAGE_BYTES + A_SPLIT_BYTES + off) = make_uint2(pack2(lx, ly), pack2(lz, lw));
        }
    };
    auto load_B_async = [&](int chunk, int stage) {
        uint32_t bh = smem_u + OFF_B + stage * B_STAGE_BYTES;
        uint32_t bl = bh + B_SPLIT_BYTES;
#pragma unroll
        for (int i = 0; i < 2; i++) {
            uint32_t off = (uint32_t)(brow[i] * (SBP * 2) + bseg[i] * 16);
            int gsrc = (chunk * 32 + brow[i]) * (HD / 8) + bseg[i];
            cp_async16(bh + off, &g_Bh4[gsrc]);
            cp_async16(bl + off, &g_Bl4[gsrc]);
        }
        cp_commit();
    };

    float acc[2][4][4];
#pragma unroll
    for (int im = 0; im < 2; im++)
#pragma unroll
        for (int in = 0; in < 4; in++)
#pragma unroll
            for (int j = 0; j < 4; j++) acc[im][in][j] = 0.0f;

    // prologue: fill stage 0
    load_A(0);
    load_B_async(0, 0);
    store_A(0);
    cp_wait0();
    __syncthreads();

    int cur = 0;
    for (int chunk = 0; chunk < 8; chunk++) {
        int nxt = cur ^ 1;
        if (chunk < 7) {
            load_A(chunk + 1);
            load_B_async(chunk + 1, nxt);
        }
        uint32_t ah_b = smem_u + cur * A_STAGE_BYTES;
        uint32_t al_b = ah_b + A_SPLIT_BYTES;
        uint32_t bh_b = smem_u + OFF_B + cur * B_STAGE_BYTES;
        uint32_t bl_b = bh_b + B_SPLIT_BYTES;
#pragma unroll
        for (int ks = 0; ks < 2; ks++) {
            // B frags via x4.trans: lanes 0-15 -> k rows at col base, 16-31 -> col base+8
            uint32_t bh[4][2], bl[4][2];
#pragma unroll
            for (int ip = 0; ip < 2; ip++) {
                uint32_t row = (uint32_t)(ks * 16 + (lane & 15));
                uint32_t col = (uint32_t)(warp_n * 32 + ip * 16 + ((lane >> 4) << 3));
                uint32_t off = (row * SBP + col) * 2;
                uint32_t r[4];
                ldsm_x4t(r, bh_b + off);
                bh[2 * ip][0] = r[0]; bh[2 * ip][1] = r[1];
                bh[2 * ip + 1][0] = r[2]; bh[2 * ip + 1][1] = r[3];
                ldsm_x4t(r, bl_b + off);
                bl[2 * ip][0] = r[0]; bl[2 * ip][1] = r[1];
                bl[2 * ip + 1][0] = r[2]; bl[2 * ip + 1][1] = r[3];
            }
            uint32_t ahf[2][4], alf[2][4];
#pragma unroll
            for (int im = 0; im < 2; im++) {
                uint32_t row = warp_m * 32 + im * 16 + (lane & 15);
                uint32_t off = (row * SAP + ks * 16 + (lane >> 4) * 8) * 2;
                ldsm_x4(ahf[im], ah_b + off);
                ldsm_x4(alf[im], al_b + off);
            }
#pragma unroll
            for (int im = 0; im < 2; im++)
#pragma unroll
                for (int in = 0; in < 4; in++) {
                    mma16816(acc[im][in], ahf[im], bh[in]);
                    mma16816(acc[im][in], ahf[im], bl[in]);
                    mma16816(acc[im][in], alf[im], bh[in]);
                }
        }
        if (chunk < 7) {
            store_A(nxt);
            cp_wait0();
        }
        __syncthreads();
        cur = nxt;
    }

    // ---- epilogue: store ft fp16 + fused el/er (warp_n == head)
#pragma unroll
    for (int im = 0; im < 2; im++) {
        int r0 = block_row + warp_m * 32 + im * 16 + (lane >> 2);
        int r1 = r0 + 8;
        float sl0 = 0.f, sr0 = 0.f, sl1 = 0.f, sr1 = 0.f;
#pragma unroll
        for (int in = 0; in < 4; in++) {
            int col = warp_n * 32 + in * 8 + (lane & 3) * 2;
            float c0 = acc[im][in][0], c1 = acc[im][in][1];
            float c2 = acc[im][in][2], c3 = acc[im][in][3];
            float a0 = sal[col], a1 = sal[col + 1];
            float b0 = sar[col], b1 = sar[col + 1];
            sl0 += c0 * a0 + c1 * a1;  sr0 += c0 * b0 + c1 * b1;
            sl1 += c2 * a0 + c3 * a1;  sr1 += c2 * b0 + c3 * b1;
            if (r0 < M) *(__half2*)&g_fth[(size_t)r0 * HD + col] = __floats2half2_rn(c0, c1);
            if (r1 < M) *(__half2*)&g_fth[(size_t)r1 * HD + col] = __floats2half2_rn(c2, c3);
        }
#pragma unroll
        for (int o = 1; o <= 2; o <<= 1) {
            sl0 += __shfl_xor_sync(0xffffffffu, sl0, o);
            sr0 += __shfl_xor_sync(0xffffffffu, sr0, o);
            sl1 += __shfl_xor_sync(0xffffffffu, sl1, o);
            sr1 += __shfl_xor_sync(0xffffffffu, sr1, o);
        }
        if ((lane & 3) == 0) {
            if (r0 < M) { g_el[r0 * NHEADS + warp_n] = sl0; g_er[r0 * NHEADS + warp_n] = sr0; }
            if (r1 < M) { g_el[r1 * NHEADS + warp_n] = sl1; g_er[r1 * NHEADS + warp_n] = sr1; }
        }
    }
}

// ---------------- K4: edge exp + segment sum (2 edges/thread, vector RED) ----
__global__ void edge_exp_kernel(const int* __restrict__ src, const int* __restrict__ dst,
                                int E) {
    int half = (E + 1) >> 1;
    int t = blockIdx.x * blockDim.x + threadIdx.x;
    if (t >= half) return;
    int e2 = t + half;
    int s0 = __ldg(&src[t]), d0 = __ldg(&dst[t]);
    int s1 = 0, d1 = 0;
    bool has2 = (e2 < E);
    if (has2) { s1 = __ldg(&src[e2]); d1 = __ldg(&dst[e2]); }
    float4 l0 = *(const float4*)&g_el[s0 * NHEADS];
    float4 r0 = *(const float4*)&g_er[d0 * NHEADS];
    float4 l1 = make_float4(0, 0, 0, 0), r1 = make_float4(0, 0, 0, 0);
    if (has2) { l1 = *(const float4*)&g_el[s1 * NHEADS]; r1 = *(const float4*)&g_er[d1 * NHEADS]; }

    float a0 = l0.x + r0.x, a1 = l0.y + r0.y, a2 = l0.z + r0.z, a3 = l0.w + r0.w;
    a0 = a0 > 0.f ? a0 : NEG_SLOPE * a0;
    a1 = a1 > 0.f ? a1 : NEG_SLOPE * a1;
    a2 = a2 > 0.f ? a2 : NEG_SLOPE * a2;
    a3 = a3 > 0.f ? a3 : NEG_SLOPE * a3;
    // logits bounded (|x| << 88): exp without max shift is mathematically identical
    float ea0 = __expf(a0), ea1 = __expf(a1), ea2 = __expf(a2), ea3 = __expf(a3);
    *(float4*)&g_eexp[(size_t)t * NHEADS] = make_float4(ea0, ea1, ea2, ea3);
    asm volatile("red.global.add.v4.f32 [%0], {%1, %2, %3, %4};"
                 :: "l"(&g_esum[d0 * NHEADS]), "f"(ea0), "f"(ea1), "f"(ea2), "f"(ea3) : "memory");

    if (has2) {
        float b0 = l1.x + r1.x, b1 = l1.y + r1.y, b2 = l1.z + r1.z, b3 = l1.w + r1.w;
        b0 = b0 > 0.f ? b0 : NEG_SLOPE * b0;
        b1 = b1 > 0.f ? b1 : NEG_SLOPE * b1;
        b2 = b2 > 0.f ? b2 : NEG_SLOPE * b2;
        b3 = b3 > 0.f ? b3 : NEG_SLOPE * b3;
        float eb0 = __expf(b0), eb1 = __expf(b1), eb2 = __expf(b2), eb3 = __expf(b3);
        *(float4*)&g_eexp[(size_t)e2 * NHEADS] = make_float4(eb0, eb1, eb2, eb3);
        asm volatile("red.global.add.v4.f32 [%0], {%1, %2, %3, %4};"
                     :: "l"(&g_esum[d1 * NHEADS]), "f"(eb0), "f"(eb1), "f"(eb2), "f"(eb3) : "memory");
    }
}

// ---------------- K5: reciprocal ---------------------------------------------
__global__ void inv_kernel(int n4) {
    int i = blockIdx.x * blockDim.x + threadIdx.x;
    if (i >= n4) return;
    float s = g_esum[i];
    g_inv[i] = (s > 0.f) ? (1.0f / s) : 0.0f;
}

// ---------------- K6: weighted aggregation (8 threads/edge, fp16 ft, v4 RED) --
// PROVEN R7/R11 shape: thread j of 8 owns output dims [4j,4j+4): per head loads
// one uint2 (4 halves); fp32 FFMA fold; one v4 RED.
__global__ void agg_kernel(const int* __restrict__ src, const int* __restrict__ dst,
                           float* __restrict__ out, int E) {
    int gtid = blockIdx.x * blockDim.x + threadIdx.x;
    int e = gtid >> 3;
    int j = gtid & 7;
    if (e >= E) return;
    int s = __ldg(&src[e]), d = __ldg(&dst[e]);
    float4 ex = *(const float4*)&g_eexp[(size_t)e * NHEADS];
    float4 iv = *(const float4*)&g_inv[d * NHEADS];
    float w0 = 0.25f * ex.x * iv.x;
    float w1 = 0.25f * ex.y * iv.y;
    float w2 = 0.25f * ex.z * iv.z;
    float w3 = 0.25f * ex.w * iv.w;
    const uint2* f2 = (const uint2*)&g_fth[(size_t)s * HD];
    uint2 u0 = f2[j], u1 = f2[8 + j], u2 = f2[16 + j], u3 = f2[24 + j];
    float2 f0a = __half22float2(*(__half2*)&u0.x), f0b = __half22float2(*(__half2*)&u0.y);
    float2 f1a = __half22float2(*(__half2*)&u1.x), f1b = __half22float2(*(__half2*)&u1.y);
    float2 f2a = __half22float2(*(__half2*)&u2.x), f2b = __half22float2(*(__half2*)&u2.y);
    float2 f3a = __half22float2(*(__half2*)&u3.x), f3b = __half22float2(*(__half2*)&u3.y);
    float vx = w0 * f0a.x + w1 * f1a.x + w2 * f2a.x + w3 * f3a.x;
    float vy = w0 * f0a.y + w1 * f1a.y + w2 * f2a.y + w3 * f3a.y;
    float vz = w0 * f0b.x + w1 * f1b.x + w2 * f2b.x + w3 * f3b.x;
    float vw = w0 * f0b.y + w1 * f1b.y + w2 * f2b.y + w3 * f3b.y;
    float* op = &out[(size_t)d * ODIM + j * 4];
    asm volatile("red.global.add.v4.f32 [%0], {%1, %2, %3, %4};"
                 :: "l"(op), "f"(vx), "f"(vy), "f"(vz), "f"(vw) : "memory");
}

// ---------------- launch ------------------------------------------------------
extern "C" void kernel_launch(void* const* d_in, const int* in_sizes, int n_in,
                              void* d_out, int out_size) {
    const float* feat = (const float*)d_in[0];
    const float* W    = (const float*)d_in[1];
    const float* al   = (const float*)d_in[2];
    const float* ar   = (const float*)d_in[3];
    const int*   src  = (const int*)d_in[4];
    const int*   dst  = (const int*)d_in[5];
    float*       out  = (float*)d_out;

    int n = in_sizes[0] / IN_DIM;
    int E = in_sizes[4];

    // K0: init esum + out + W split (merged)
    {
        int threads = 256;
        int blocks = (n * ODIM + threads - 1) / threads;
        if (blocks > 8192) blocks = 8192;
        init_prep_kernel<<<blocks, threads>>>(out, W, n);
    }
    // K1: pipelined mma.sync GEMM + fused el/er
    {
        cudaFuncSetAttribute(gemm_mma_kernel,
                             cudaFuncAttributeMaxDynamicSharedMemorySize, GEMM_SMEM_TOTAL);
        gemm_mma_kernel<<<(n + 63) / 64, 256, GEMM_SMEM_TOTAL>>>(feat, al, ar, n);
    }
    // K4: exp + segment sum (2 edges/thread)
    {
        int half = (E + 1) >> 1;
        edge_exp_kernel<<<(half + 255) / 256, 256>>>(src, dst, E);
    }
    // K5: reciprocal
    {
        int n4 = n * NHEADS;
        inv_kernel<<<(n4 + 255) / 256, 256>>>(n4);
    }
    // K6: aggregation (8 threads per edge, fp16 ft)
    {
        long long totalThreads = (long long)E * 8;
        int blocks = (int)((totalThreads + 255) / 256);
        agg_kernel<<<blocks, 256>>>(src, dst, out, E);
    }
}